// round 14
// baseline (speedup 1.0000x reference)
#include <cuda_runtime.h>
#include <math.h>
#include <stdint.h>

#define NUM_USERS 162541
#define NUM_ITEMS 59047
#define N_NODES   221588
#define DIM       128
#define N_EDGES   100000
#define BATCH     16384
#define MAXL1     132768
#define MAXL2     32768
#define NBLK      296        // persistent: 2 blocks/SM guaranteed resident
#define SA_STR    132
#define SB_STR    136

// smem layout (floats): sA[8448] | sB[2176] | sWs[512] | sWd[512] | sNode[64 ints]
#define OFF_SB    8448
#define OFF_SWS   10624
#define OFF_SWD   11136
#define OFF_SNODE 11648
#define SMEMF     (OFF_SNODE + 64)
#define SMEMB     (SMEMF * 4)

// ---------------- scratch (device globals; zero on entry, self-cleaning) ----
__device__ float g_h1 [(size_t)N_NODES * DIM];   // h1; later h2
__device__ int g_need1[N_NODES], g_need2[N_NODES];
__device__ int g_head1[N_NODES], g_head2[N_NODES];   // linked-list heads (+1; 0=end)
__device__ int g_nxt1[N_EDGES], g_nxt2[N_EDGES];
__device__ int g_list1[MAXL1], g_list2[MAXL2];
__device__ int g_cnt1, g_cnt2;
__device__ float g_ws1[4 * DIM], g_wd1[4 * DIM];
__device__ float g_ws2[DIM],     g_wd2[DIM];
__device__ unsigned g_gen, g_cntb;

// ---------------- helpers ---------------------------------------------------
__device__ __forceinline__ float eluf(float x)  { return x > 0.f ? x : expm1f(x); }
__device__ __forceinline__ float lrelu(float x) { return x > 0.f ? x : 0.2f * x; }
__device__ __forceinline__ float wsum(float v) {
    #pragma unroll
    for (int o = 16; o; o >>= 1) v += __shfl_xor_sync(0xffffffffu, v, o);
    return v;
}
__device__ __forceinline__ const float* xrow(int n, const float* uT, const float* iT) {
    return (n < NUM_USERS) ? uT + (size_t)n * DIM
                           : iT + (size_t)(n - NUM_USERS) * DIM;
}
__device__ __forceinline__ void mma8(float& c0, float& c1, float& c2, float& c3,
    uint32_t a0, uint32_t a1, uint32_t a2, uint32_t a3, uint32_t b0, uint32_t b1) {
    asm volatile("mma.sync.aligned.m16n8k8.row.col.f32.tf32.tf32.f32 "
        "{%0,%1,%2,%3}, {%4,%5,%6,%7}, {%8,%9}, {%0,%1,%2,%3};\n"
        : "+f"(c0), "+f"(c1), "+f"(c2), "+f"(c3)
        : "r"(a0), "r"(a1), "r"(a2), "r"(a3), "r"(b0), "r"(b1));
}
__device__ __forceinline__ void gridbar() {
    __syncthreads();
    if (threadIdx.x == 0) {
        __threadfence();
        unsigned gen = *((volatile unsigned*)&g_gen);
        if (atomicAdd(&g_cntb, 1) == NBLK - 1) {
            g_cntb = 0;
            __threadfence();
            atomicAdd(&g_gen, 1);
        } else {
            while (*((volatile unsigned*)&g_gen) == gen) { }
        }
        __threadfence();
    }
    __syncthreads();
}

// ---------------- THE kernel: whole model in one persistent launch ----------
__global__ __launch_bounds__(256, 2)
void mono_k(const float* __restrict__ W1, const float* __restrict__ aS1,
            const float* __restrict__ aD1, const float* __restrict__ W2,
            const float* __restrict__ aS2, const float* __restrict__ aD2,
            const int* __restrict__ uidx, const int* __restrict__ iidx,
            const int* __restrict__ ei,
            const float* __restrict__ uT, const float* __restrict__ iT,
            const float* __restrict__ bias1, const float* __restrict__ bias2,
            float* __restrict__ res)
{
    extern __shared__ float smem[];
    float* sA  = smem;
    float* sB  = smem + OFF_SB;
    float* sWs = smem + OFF_SWS;
    float* sWd = smem + OFF_SWD;
    int* sNode = (int*)(smem + OFF_SNODE);

    const int tid = threadIdx.x;
    const int w   = tid >> 5, lane = tid & 31;
    const int gstride = NBLK * 256;

    // ===== P0: weight fold (block 0) + batch claims =====
    if (blockIdx.x == 0 && tid < 128) {
        int k = tid;
        #pragma unroll
        for (int h = 0; h < 4; h++) {
            float s = 0.f, d = 0.f;
            #pragma unroll
            for (int c = 0; c < 32; c++) {
                float wv = W1[k * DIM + h * 32 + c];
                s = fmaf(wv, aS1[h * 32 + c], s);
                d = fmaf(wv, aD1[h * 32 + c], d);
            }
            g_ws1[h * DIM + k] = s;
            g_wd1[h * DIM + k] = d;
        }
        float s2 = 0.f, d2 = 0.f;
        for (int j = 0; j < DIM; j++) {
            float wv = W2[k * DIM + j];
            s2 = fmaf(wv, aS2[j], s2);
            d2 = fmaf(wv, aD2[j], d2);
        }
        g_ws2[k] = s2;
        g_wd2[k] = d2;
    }
    for (int i = blockIdx.x * 256 + tid; i < BATCH; i += gstride) {
        int u = uidx[i], v = iidx[i] + NUM_USERS;
        if (atomicExch(&g_need2[u], 1) == 0) g_list2[atomicAdd(&g_cnt2, 1)] = u;
        if (atomicExch(&g_need1[u], 1) == 0) g_list1[atomicAdd(&g_cnt1, 1)] = u;
        if (atomicExch(&g_need2[v], 1) == 0) g_list2[atomicAdd(&g_cnt2, 1)] = v;
        if (atomicExch(&g_need1[v], 1) == 0) g_list1[atomicAdd(&g_cnt1, 1)] = v;
    }
    gridbar();

    // ===== P1: adj2 chains + claim srcs into need1 =====
    for (int e = blockIdx.x * 256 + tid; e < N_EDGES; e += gstride) {
        int d = ei[N_EDGES + e];
        if (g_need2[d]) {
            g_nxt2[e] = atomicExch(&g_head2[d], e + 1);
            int s = ei[e];
            if (atomicExch(&g_need1[s], 1) == 0) g_list1[atomicAdd(&g_cnt1, 1)] = s;
        }
    }
    gridbar();

    // ===== P2: adj1 chains =====
    for (int e = blockIdx.x * 256 + tid; e < N_EDGES; e += gstride) {
        int d = ei[N_EDGES + e];
        if (g_need1[d]) g_nxt1[e] = atomicExch(&g_head1[d], e + 1);
    }
    gridbar();

    // ===== F1: layer-1 gather + TF32 GEMM, 16-node tiles =====
    for (int i = tid; i < 512; i += 256) { sWs[i] = g_ws1[i]; sWd[i] = g_wd1[i]; }
    __syncthreads();
    const int cnt1 = g_cnt1;
    for (int t0 = blockIdx.x; t0 * 16 < cnt1; t0 += NBLK) {
        const int row0 = t0 * 16;
        if (tid < 16) sNode[tid] = (row0 + tid < cnt1) ? g_list1[row0 + tid] : -1;
        __syncthreads();

        for (int j2 = 0; j2 < 2; j2++) {
            int slot = w * 2 + j2;
            int d = sNode[slot];
            if (d < 0) {
                #pragma unroll
                for (int h = 0; h < 4; h++) {
                    float* o = sA + (size_t)(h * 16 + slot) * SA_STR;
                    o[lane] = 0.f; o[lane + 32] = 0.f; o[lane + 64] = 0.f; o[lane + 96] = 0.f;
                }
                continue;
            }
            const float* xd = xrow(d, uT, iT);
            float v0 = xd[lane], v1 = xd[lane + 32], v2 = xd[lane + 64], v3 = xd[lane + 96];
            float bd[4], den[4], acc[4][4];
            #pragma unroll
            for (int h = 0; h < 4; h++) {
                float ad = wsum(v0 * sWs[h * 128 + lane] + v1 * sWs[h * 128 + lane + 32] +
                                v2 * sWs[h * 128 + lane + 64] + v3 * sWs[h * 128 + lane + 96]);
                bd[h]    = wsum(v0 * sWd[h * 128 + lane] + v1 * sWd[h * 128 + lane + 32] +
                                v2 * sWd[h * 128 + lane + 64] + v3 * sWd[h * 128 + lane + 96]);
                float ww = expf(lrelu(ad + bd[h]));
                den[h] = ww;
                acc[h][0] = ww * v0; acc[h][1] = ww * v1;
                acc[h][2] = ww * v2; acc[h][3] = ww * v3;
            }
            int p = g_head1[d];
            while (p) {
                int e = p - 1;
                int s = ei[e];
                p = g_nxt1[e];
                const float* xs = xrow(s, uT, iT);
                float c0 = xs[lane], c1 = xs[lane + 32], c2 = xs[lane + 64], c3 = xs[lane + 96];
                #pragma unroll
                for (int h = 0; h < 4; h++) {
                    float as = wsum(c0 * sWs[h * 128 + lane] + c1 * sWs[h * 128 + lane + 32] +
                                    c2 * sWs[h * 128 + lane + 64] + c3 * sWs[h * 128 + lane + 96]);
                    float q = expf(lrelu(as + bd[h]));
                    den[h] += q;
                    acc[h][0] += q * c0; acc[h][1] += q * c1;
                    acc[h][2] += q * c2; acc[h][3] += q * c3;
                }
            }
            #pragma unroll
            for (int h = 0; h < 4; h++) {
                float inv = 1.f / (den[h] + 1e-16f);
                float* o = sA + (size_t)(h * 16 + slot) * SA_STR;
                o[lane]      = acc[h][0] * inv;  o[lane + 32] = acc[h][1] * inv;
                o[lane + 64] = acc[h][2] * inv;  o[lane + 96] = acc[h][3] * inv;
            }
            if (lane == 0) { g_head1[d] = 0; g_need1[d] = 0; }   // self-clean
        }
        __syncthreads();

        // GEMM: warp -> head w>>1, n-half (w&1)*16
        const int h  = w >> 1;
        const int nh = (w & 1) * 16;
        const int g  = lane >> 2;
        const int t  = lane & 3;
        float acc[2][4];
        #pragma unroll
        for (int i = 0; i < 2; i++)
            #pragma unroll
            for (int j = 0; j < 4; j++) acc[i][j] = 0.f;

        const int brow = tid >> 4;
        const int bcol = (tid & 15) * 8;
        const float* sAh = sA + (size_t)h * 16 * SA_STR;
        for (int kk = 0; kk < DIM; kk += 16) {
            *(float4*)&sB[brow * SB_STR + bcol]     = *(const float4*)(W1 + (size_t)(kk + brow) * DIM + bcol);
            *(float4*)&sB[brow * SB_STR + bcol + 4] = *(const float4*)(W1 + (size_t)(kk + brow) * DIM + bcol + 4);
            __syncthreads();
            #pragma unroll
            for (int k8 = 0; k8 < 16; k8 += 8) {
                uint32_t a0 = __float_as_uint(sAh[(g)     * SA_STR + kk + k8 + t]);
                uint32_t a1 = __float_as_uint(sAh[(g + 8) * SA_STR + kk + k8 + t]);
                uint32_t a2 = __float_as_uint(sAh[(g)     * SA_STR + kk + k8 + t + 4]);
                uint32_t a3 = __float_as_uint(sAh[(g + 8) * SA_STR + kk + k8 + t + 4]);
                #pragma unroll
                for (int nt = 0; nt < 2; nt++) {
                    int n = h * 32 + nh + nt * 8 + g;
                    uint32_t b0 = __float_as_uint(sB[(k8 + t)     * SB_STR + n]);
                    uint32_t b1 = __float_as_uint(sB[(k8 + t + 4) * SB_STR + n]);
                    mma8(acc[nt][0], acc[nt][1], acc[nt][2], acc[nt][3],
                         a0, a1, a2, a3, b0, b1);
                }
            }
            __syncthreads();
        }
        #pragma unroll
        for (int nt = 0; nt < 2; nt++) {
            int col = h * 32 + nh + nt * 8 + 2 * t;
            float b0 = bias1[col], b1 = bias1[col + 1];
            if (row0 + g < cnt1) {
                float* o = g_h1 + (size_t)sNode[g] * DIM + col;
                *(float2*)o = make_float2(eluf(acc[nt][0] + b0), eluf(acc[nt][1] + b1));
            }
            if (row0 + g + 8 < cnt1) {
                float* o = g_h1 + (size_t)sNode[g + 8] * DIM + col;
                *(float2*)o = make_float2(eluf(acc[nt][2] + b0), eluf(acc[nt][3] + b1));
            }
        }
        __syncthreads();   // protect sNode/sA before next tile
    }
    gridbar();

    // ===== F2: layer-2 gather + TF32 GEMM, 64-node tiles =====
    if (tid < 128) { sWs[tid] = g_ws2[tid]; sWd[tid] = g_wd2[tid]; }
    __syncthreads();
    const int cnt2 = g_cnt2;
    for (int t0 = blockIdx.x; t0 * 64 < cnt2; t0 += NBLK) {
        const int row0 = t0 * 64;
        if (tid < 64) sNode[tid] = (row0 + tid < cnt2) ? g_list2[row0 + tid] : -1;
        __syncthreads();

        for (int j8 = 0; j8 < 8; j8++) {
            int slot = w * 8 + j8;
            int d = sNode[slot];
            float* o = sA + (size_t)slot * SA_STR;
            if (d < 0) {
                o[lane] = 0.f; o[lane + 32] = 0.f; o[lane + 64] = 0.f; o[lane + 96] = 0.f;
                continue;
            }
            float wr0 = sWs[lane],      wr1 = sWs[lane + 32];
            float wr2 = sWs[lane + 64], wr3 = sWs[lane + 96];
            const float* hd = g_h1 + (size_t)d * DIM;
            float v0 = hd[lane], v1 = hd[lane + 32], v2 = hd[lane + 64], v3 = hd[lane + 96];
            float ad  = wsum(v0 * wr0 + v1 * wr1 + v2 * wr2 + v3 * wr3);
            float b2d = wsum(v0 * sWd[lane] + v1 * sWd[lane + 32] +
                             v2 * sWd[lane + 64] + v3 * sWd[lane + 96]);
            float ww = expf(lrelu(ad + b2d));
            float den = ww;
            float a0 = ww * v0, a1 = ww * v1, a2 = ww * v2, a3 = ww * v3;
            int p = g_head2[d];
            while (p) {
                int e = p - 1;
                int s = ei[e];
                p = g_nxt2[e];
                const float* hs = g_h1 + (size_t)s * DIM;
                float c0 = hs[lane], c1 = hs[lane + 32], c2 = hs[lane + 64], c3 = hs[lane + 96];
                float as = wsum(c0 * wr0 + c1 * wr1 + c2 * wr2 + c3 * wr3);
                float q = expf(lrelu(as + b2d));
                den += q;
                a0 += q * c0; a1 += q * c1; a2 += q * c2; a3 += q * c3;
            }
            float inv = 1.f / (den + 1e-16f);
            o[lane]      = a0 * inv;  o[lane + 32] = a1 * inv;
            o[lane + 64] = a2 * inv;  o[lane + 96] = a3 * inv;
            if (lane == 0) { g_head2[d] = 0; g_need2[d] = 0; }   // self-clean
        }
        __syncthreads();

        // GEMM: warp -> m-tile (w>>1)*16, n-half (w&1)*64
        const int g  = lane >> 2;
        const int t  = lane & 3;
        const int mt = (w >> 1) * 16;
        const int nh = (w & 1) * 64;
        float acc[8][4];
        #pragma unroll
        for (int i = 0; i < 8; i++)
            #pragma unroll
            for (int j = 0; j < 4; j++) acc[i][j] = 0.f;

        const int brow = tid >> 4;
        const int bcol = (tid & 15) * 8;
        for (int kk = 0; kk < DIM; kk += 16) {
            *(float4*)&sB[brow * SB_STR + bcol]     = *(const float4*)(W2 + (size_t)(kk + brow) * DIM + bcol);
            *(float4*)&sB[brow * SB_STR + bcol + 4] = *(const float4*)(W2 + (size_t)(kk + brow) * DIM + bcol + 4);
            __syncthreads();
            #pragma unroll
            for (int k8 = 0; k8 < 16; k8 += 8) {
                uint32_t a0 = __float_as_uint(sA[(mt + g)     * SA_STR + kk + k8 + t]);
                uint32_t a1 = __float_as_uint(sA[(mt + g + 8) * SA_STR + kk + k8 + t]);
                uint32_t a2 = __float_as_uint(sA[(mt + g)     * SA_STR + kk + k8 + t + 4]);
                uint32_t a3 = __float_as_uint(sA[(mt + g + 8) * SA_STR + kk + k8 + t + 4]);
                #pragma unroll
                for (int nt = 0; nt < 8; nt++) {
                    int n = nh + nt * 8 + g;
                    uint32_t b0 = __float_as_uint(sB[(k8 + t)     * SB_STR + n]);
                    uint32_t b1 = __float_as_uint(sB[(k8 + t + 4) * SB_STR + n]);
                    mma8(acc[nt][0], acc[nt][1], acc[nt][2], acc[nt][3],
                         a0, a1, a2, a3, b0, b1);
                }
            }
            __syncthreads();
        }
        #pragma unroll
        for (int nt = 0; nt < 8; nt++) {
            int col = nh + nt * 8 + 2 * t;
            float b0 = bias2[col], b1 = bias2[col + 1];
            if (row0 + mt + g < cnt2) {
                float* o = g_h1 + (size_t)sNode[mt + g] * DIM + col;     // h2 aliases h1
                *(float2*)o = make_float2(eluf(acc[nt][0] + b0), eluf(acc[nt][1] + b1));
            }
            if (row0 + mt + g + 8 < cnt2) {
                float* o = g_h1 + (size_t)sNode[mt + g + 8] * DIM + col;
                *(float2*)o = make_float2(eluf(acc[nt][2] + b0), eluf(acc[nt][3] + b1));
            }
        }
        __syncthreads();
    }
    gridbar();

    // ===== FIN: dot + sigmoid; reset counters for next replay =====
    if (blockIdx.x == 0 && tid == 0) { g_cnt1 = 0; g_cnt2 = 0; }
    for (int b = blockIdx.x * 8 + w; b < BATCH; b += NBLK * 8) {
        const float* ru = g_h1 + (size_t)uidx[b] * DIM;
        const float* rv = g_h1 + (size_t)(iidx[b] + NUM_USERS) * DIM;
        float dot = ru[lane]      * rv[lane]
                  + ru[lane + 32] * rv[lane + 32]
                  + ru[lane + 64] * rv[lane + 64]
                  + ru[lane + 96] * rv[lane + 96];
        dot = wsum(dot);
        if (lane == 0) res[b] = 1.f / (1.f + expf(-dot));
    }
}

// ---------------- launch -----------------------------------------------------
extern "C" void kernel_launch(void* const* d_in, const int* in_sizes, int n_in,
                              void* d_out, int out_size)
{
    const int*   uidx  = (const int*)  d_in[0];
    const int*   iidx  = (const int*)  d_in[1];
    const int*   ei    = (const int*)  d_in[2];
    const float* userT = (const float*)d_in[3];
    const float* itemT = (const float*)d_in[4];
    const float* W1    = (const float*)d_in[5];
    const float* attS1 = (const float*)d_in[6];
    const float* attD1 = (const float*)d_in[7];
    const float* bias1 = (const float*)d_in[8];
    const float* W2    = (const float*)d_in[9];
    const float* attS2 = (const float*)d_in[10];
    const float* attD2 = (const float*)d_in[11];
    const float* bias2 = (const float*)d_in[12];
    float* res = (float*)d_out;

    cudaFuncSetAttribute(mono_k, cudaFuncAttributeMaxDynamicSharedMemorySize, SMEMB);
    mono_k<<<NBLK, 256, SMEMB>>>(W1, attS1, attD1, W2, attS2, attD2,
                                 uidx, iidx, ei, userT, itemT, bias1, bias2, res);
}

// round 16
// speedup vs baseline: 1.2114x; 1.2114x over previous
#include <cuda_runtime.h>
#include <math.h>
#include <stdint.h>

#define NUM_USERS 162541
#define NUM_ITEMS 59047
#define N_NODES   221588
#define DIM       128
#define N_EDGES   100000
#define BATCH     16384
#define MAXL1     132768
#define MAXL2     32768
#define NBLK      296        // persistent prep grid: 2 blocks/SM resident
#define SA_STR    132        // conflict-free mma A frags
#define SB_STR    136        // conflict-free mma B frags

// ---------------- scratch (device globals; zero on entry, self-cleaning) ----
__device__ float g_h1 [(size_t)N_NODES * DIM];   // h1; later h2
__device__ int g_need1[N_NODES], g_need2[N_NODES];
__device__ int g_head1[N_NODES], g_head2[N_NODES];   // chain heads (+1; 0 = end)
__device__ int g_nxt1[N_EDGES], g_nxt2[N_EDGES];
__device__ int g_list1[MAXL1], g_list2[MAXL2];
__device__ int g_cnt1, g_cnt2;
__device__ float g_ws1[4 * DIM], g_wd1[4 * DIM];
__device__ float g_ws2[DIM],     g_wd2[DIM];
__device__ unsigned g_gen, g_cntb;

// ---------------- helpers ---------------------------------------------------
__device__ __forceinline__ float eluf(float x)  { return x > 0.f ? x : expm1f(x); }
__device__ __forceinline__ float lrelu(float x) { return x > 0.f ? x : 0.2f * x; }
__device__ __forceinline__ float wsum(float v) {
    #pragma unroll
    for (int o = 16; o; o >>= 1) v += __shfl_xor_sync(0xffffffffu, v, o);
    return v;
}
__device__ __forceinline__ const float* xrow(int n, const float* uT, const float* iT) {
    return (n < NUM_USERS) ? uT + (size_t)n * DIM
                           : iT + (size_t)(n - NUM_USERS) * DIM;
}
__device__ __forceinline__ void mma8(float& c0, float& c1, float& c2, float& c3,
    uint32_t a0, uint32_t a1, uint32_t a2, uint32_t a3, uint32_t b0, uint32_t b1) {
    asm volatile("mma.sync.aligned.m16n8k8.row.col.f32.tf32.tf32.f32 "
        "{%0,%1,%2,%3}, {%4,%5,%6,%7}, {%8,%9}, {%0,%1,%2,%3};\n"
        : "+f"(c0), "+f"(c1), "+f"(c2), "+f"(c3)
        : "r"(a0), "r"(a1), "r"(a2), "r"(a3), "r"(b0), "r"(b1));
}
__device__ __forceinline__ void gridbar() {
    __syncthreads();
    if (threadIdx.x == 0) {
        __threadfence();
        unsigned gen = *((volatile unsigned*)&g_gen);
        if (atomicAdd(&g_cntb, 1) == NBLK - 1) {
            g_cntb = 0;
            __threadfence();
            atomicAdd(&g_gen, 1);
        } else {
            while (*((volatile unsigned*)&g_gen) == gen) { }
        }
        __threadfence();
    }
    __syncthreads();
}

// ---------------- 1: chain-building prep (3 phases, 1 launch, 2 gridbars) ----
__global__ __launch_bounds__(256)
void prep_k(const float* __restrict__ W1, const float* __restrict__ aS1,
            const float* __restrict__ aD1, const float* __restrict__ W2,
            const float* __restrict__ aS2, const float* __restrict__ aD2,
            const int* __restrict__ uidx, const int* __restrict__ iidx,
            const int* __restrict__ ei)
{
    const int tid = threadIdx.x;
    const int gstride = NBLK * 256;

    // P0: weight fold (block 0) + batch claims (list-append on first claim)
    if (blockIdx.x == 0 && tid < 128) {
        int k = tid;
        #pragma unroll
        for (int h = 0; h < 4; h++) {
            float s = 0.f, d = 0.f;
            #pragma unroll
            for (int c = 0; c < 32; c++) {
                float wv = W1[k * DIM + h * 32 + c];
                s = fmaf(wv, aS1[h * 32 + c], s);
                d = fmaf(wv, aD1[h * 32 + c], d);
            }
            g_ws1[h * DIM + k] = s;
            g_wd1[h * DIM + k] = d;
        }
        float s2 = 0.f, d2 = 0.f;
        for (int j = 0; j < DIM; j++) {
            float wv = W2[k * DIM + j];
            s2 = fmaf(wv, aS2[j], s2);
            d2 = fmaf(wv, aD2[j], d2);
        }
        g_ws2[k] = s2;
        g_wd2[k] = d2;
    }
    for (int i = blockIdx.x * 256 + tid; i < BATCH; i += gstride) {
        int u = uidx[i], v = iidx[i] + NUM_USERS;
        if (atomicExch(&g_need2[u], 1) == 0) g_list2[atomicAdd(&g_cnt2, 1)] = u;
        if (atomicExch(&g_need1[u], 1) == 0) g_list1[atomicAdd(&g_cnt1, 1)] = u;
        if (atomicExch(&g_need2[v], 1) == 0) g_list2[atomicAdd(&g_cnt2, 1)] = v;
        if (atomicExch(&g_need1[v], 1) == 0) g_list1[atomicAdd(&g_cnt1, 1)] = v;
    }
    gridbar();

    // P1: adj2 chains + claim srcs into need1
    for (int e = blockIdx.x * 256 + tid; e < N_EDGES; e += gstride) {
        int d = ei[N_EDGES + e];
        if (g_need2[d]) {
            g_nxt2[e] = atomicExch(&g_head2[d], e + 1);
            int s = ei[e];
            if (atomicExch(&g_need1[s], 1) == 0) g_list1[atomicAdd(&g_cnt1, 1)] = s;
        }
    }
    gridbar();

    // P2: adj1 chains
    for (int e = blockIdx.x * 256 + tid; e < N_EDGES; e += gstride) {
        int d = ei[N_EDGES + e];
        if (g_need1[d]) g_nxt1[e] = atomicExch(&g_head1[d], e + 1);
    }
}

// ---------------- 2: fused layer-1 gather + TF32-mma GEMM (R12 body) --------
// block = 32 need1 nodes. sA: [h*32+slot][k] stride SA_STR.
#define SM1_SA   (4 * 32 * SA_STR)
#define SM1_SB   (16 * SB_STR)
#define SMEM1    ((SM1_SA + SM1_SB) * 4 + 32 * 4)
__global__ __launch_bounds__(256)
void fused1_k(const float* __restrict__ uT, const float* __restrict__ iT,
              const int* __restrict__ ei,
              const float* __restrict__ W1, const float* __restrict__ bias1)
{
    extern __shared__ float smem[];
    float* sA = smem;
    float* sB = smem + SM1_SA;
    int*   sNode = (int*)(smem + SM1_SA + SM1_SB);

    const int cnt  = g_cnt1;
    const int row0 = blockIdx.x * 32;
    if (row0 >= cnt) return;
    const int tid  = threadIdx.x;
    const int w    = tid >> 5, lane = tid & 31;

    if (tid < 32) sNode[tid] = (row0 + tid < cnt) ? g_list1[row0 + tid] : -1;
    __syncthreads();

    // ---- gather: warp w -> slots w*4 .. w*4+3, chain traversal ----
    {
        float wsr[4][4], wdr[4][4];
        #pragma unroll
        for (int h = 0; h < 4; h++)
            #pragma unroll
            for (int j = 0; j < 4; j++) {
                wsr[h][j] = g_ws1[h * DIM + lane + 32 * j];
                wdr[h][j] = g_wd1[h * DIM + lane + 32 * j];
            }
        for (int j4 = 0; j4 < 4; j4++) {
            int slot = w * 4 + j4;
            int d = sNode[slot];
            if (d < 0) {
                #pragma unroll
                for (int h = 0; h < 4; h++) {
                    float* o = sA + (size_t)(h * 32 + slot) * SA_STR;
                    o[lane] = 0.f; o[lane + 32] = 0.f;
                    o[lane + 64] = 0.f; o[lane + 96] = 0.f;
                }
                continue;
            }
            const float* xd = xrow(d, uT, iT);
            float v0 = xd[lane], v1 = xd[lane + 32], v2 = xd[lane + 64], v3 = xd[lane + 96];
            float bd[4], den[4], acc[4][4];
            #pragma unroll
            for (int h = 0; h < 4; h++) {
                float ad = wsum(v0 * wsr[h][0] + v1 * wsr[h][1] +
                                v2 * wsr[h][2] + v3 * wsr[h][3]);
                bd[h]    = wsum(v0 * wdr[h][0] + v1 * wdr[h][1] +
                                v2 * wdr[h][2] + v3 * wdr[h][3]);
                float ww = expf(lrelu(ad + bd[h]));
                den[h] = ww;
                acc[h][0] = ww * v0; acc[h][1] = ww * v1;
                acc[h][2] = ww * v2; acc[h][3] = ww * v3;
            }
            int p = g_head1[d];
            while (p) {
                int e = p - 1;
                int s = ei[e];          // independent loads: dual-issue
                p = g_nxt1[e];
                const float* xs = xrow(s, uT, iT);
                float c0 = xs[lane], c1 = xs[lane + 32], c2 = xs[lane + 64], c3 = xs[lane + 96];
                #pragma unroll
                for (int h = 0; h < 4; h++) {
                    float as = wsum(c0 * wsr[h][0] + c1 * wsr[h][1] +
                                    c2 * wsr[h][2] + c3 * wsr[h][3]);
                    float q = expf(lrelu(as + bd[h]));
                    den[h] += q;
                    acc[h][0] += q * c0; acc[h][1] += q * c1;
                    acc[h][2] += q * c2; acc[h][3] += q * c3;
                }
            }
            #pragma unroll
            for (int h = 0; h < 4; h++) {
                float inv = 1.f / (den[h] + 1e-16f);
                float* o = sA + (size_t)(h * 32 + slot) * SA_STR;
                o[lane]      = acc[h][0] * inv;  o[lane + 32] = acc[h][1] * inv;
                o[lane + 64] = acc[h][2] * inv;  o[lane + 96] = acc[h][3] * inv;
            }
            if (lane == 0) { g_need1[d] = 0; g_head1[d] = 0; }   // self-clean
        }
    }
    __syncthreads();

    // ---- GEMM (tf32 mma): warp w -> head w>>1, m-half (w&1)*16 ----
    const int h     = w >> 1;
    const int mhalf = (w & 1) * 16;
    const int g     = lane >> 2;
    const int t     = lane & 3;
    float acc[4][4];
    #pragma unroll
    for (int i = 0; i < 4; i++)
        #pragma unroll
        for (int j = 0; j < 4; j++) acc[i][j] = 0.f;

    const int brow = tid >> 4;
    const int bcol = (tid & 15) * 8;
    const float* sAh = sA + (size_t)h * 32 * SA_STR;
    for (int kk = 0; kk < DIM; kk += 16) {
        *(float4*)&sB[brow * SB_STR + bcol]     = *(const float4*)(W1 + (size_t)(kk + brow) * DIM + bcol);
        *(float4*)&sB[brow * SB_STR + bcol + 4] = *(const float4*)(W1 + (size_t)(kk + brow) * DIM + bcol + 4);
        __syncthreads();
        #pragma unroll
        for (int k8 = 0; k8 < 16; k8 += 8) {
            uint32_t a0 = __float_as_uint(sAh[(mhalf + g)     * SA_STR + kk + k8 + t]);
            uint32_t a1 = __float_as_uint(sAh[(mhalf + g + 8) * SA_STR + kk + k8 + t]);
            uint32_t a2 = __float_as_uint(sAh[(mhalf + g)     * SA_STR + kk + k8 + t + 4]);
            uint32_t a3 = __float_as_uint(sAh[(mhalf + g + 8) * SA_STR + kk + k8 + t + 4]);
            #pragma unroll
            for (int nt = 0; nt < 4; nt++) {
                int n = h * 32 + nt * 8 + g;
                uint32_t b0 = __float_as_uint(sB[(k8 + t)     * SB_STR + n]);
                uint32_t b1 = __float_as_uint(sB[(k8 + t + 4) * SB_STR + n]);
                mma8(acc[nt][0], acc[nt][1], acc[nt][2], acc[nt][3],
                     a0, a1, a2, a3, b0, b1);
            }
        }
        __syncthreads();
    }

    #pragma unroll
    for (int nt = 0; nt < 4; nt++) {
        int col = h * 32 + nt * 8 + 2 * t;
        float b0 = bias1[col], b1 = bias1[col + 1];
        int s0 = mhalf + g, s1 = mhalf + g + 8;
        if (row0 + s0 < cnt) {
            float* o = g_h1 + (size_t)sNode[s0] * DIM + col;
            *(float2*)o = make_float2(eluf(acc[nt][0] + b0), eluf(acc[nt][1] + b1));
        }
        if (row0 + s1 < cnt) {
            float* o = g_h1 + (size_t)sNode[s1] * DIM + col;
            *(float2*)o = make_float2(eluf(acc[nt][2] + b0), eluf(acc[nt][3] + b1));
        }
    }
}

// ---------------- 3: fused layer-2 gather + TF32-mma GEMM (R12 body) --------
// block = 128 need2 nodes.
#define SM2_SA   (128 * SA_STR)
#define SM2_SB   (16 * SB_STR)
#define SMEM2    ((SM2_SA + SM2_SB) * 4 + 128 * 4)
__global__ __launch_bounds__(256)
void fused2_k(const int* __restrict__ ei,
              const float* __restrict__ W2, const float* __restrict__ bias2)
{
    extern __shared__ float smem[];
    float* sA = smem;
    float* sB = smem + SM2_SA;
    int*   sNode = (int*)(smem + SM2_SA + SM2_SB);

    const int cnt  = g_cnt2;
    const int row0 = blockIdx.x * 128;
    if (row0 >= cnt) return;
    const int tid  = threadIdx.x;
    const int w    = tid >> 5, lane = tid & 31;

    if (tid < 128) sNode[tid] = (row0 + tid < cnt) ? g_list2[row0 + tid] : -1;
    __syncthreads();

    // ---- gather: warp w -> slots w*16 .. w*16+15, chain traversal ----
    {
        float wr[4], wdr[4];
        #pragma unroll
        for (int j = 0; j < 4; j++) {
            wr[j]  = g_ws2[lane + 32 * j];
            wdr[j] = g_wd2[lane + 32 * j];
        }
        for (int j16 = 0; j16 < 16; j16++) {
            int slot = w * 16 + j16;
            int d = sNode[slot];
            float* o = sA + (size_t)slot * SA_STR;
            if (d < 0) {
                o[lane] = 0.f; o[lane + 32] = 0.f;
                o[lane + 64] = 0.f; o[lane + 96] = 0.f;
                continue;
            }
            const float* hd = g_h1 + (size_t)d * DIM;
            float v0 = hd[lane], v1 = hd[lane + 32], v2 = hd[lane + 64], v3 = hd[lane + 96];
            float ad  = wsum(v0 * wr[0] + v1 * wr[1] + v2 * wr[2] + v3 * wr[3]);
            float b2d = wsum(v0 * wdr[0] + v1 * wdr[1] + v2 * wdr[2] + v3 * wdr[3]);
            float ww = expf(lrelu(ad + b2d));
            float den = ww;
            float a0 = ww * v0, a1 = ww * v1, a2 = ww * v2, a3 = ww * v3;
            int p = g_head2[d];
            while (p) {
                int e = p - 1;
                int s = ei[e];
                p = g_nxt2[e];
                const float* hs = g_h1 + (size_t)s * DIM;
                float c0 = hs[lane], c1 = hs[lane + 32], c2 = hs[lane + 64], c3 = hs[lane + 96];
                float as = wsum(c0 * wr[0] + c1 * wr[1] + c2 * wr[2] + c3 * wr[3]);
                float q = expf(lrelu(as + b2d));
                den += q;
                a0 += q * c0; a1 += q * c1; a2 += q * c2; a3 += q * c3;
            }
            float inv = 1.f / (den + 1e-16f);
            o[lane]      = a0 * inv;  o[lane + 32] = a1 * inv;
            o[lane + 64] = a2 * inv;  o[lane + 96] = a3 * inv;
            if (lane == 0) { g_need2[d] = 0; g_head2[d] = 0; }   // self-clean
        }
    }
    __syncthreads();

    // ---- GEMM (tf32 mma): warp w -> rows w*16..+15, all 128 cols ----
    const int g = lane >> 2;
    const int t = lane & 3;
    const int mrow = w * 16;
    float acc[16][4];
    #pragma unroll
    for (int i = 0; i < 16; i++)
        #pragma unroll
        for (int j = 0; j < 4; j++) acc[i][j] = 0.f;

    const int brow = tid >> 4;
    const int bcol = (tid & 15) * 8;
    for (int kk = 0; kk < DIM; kk += 16) {
        *(float4*)&sB[brow * SB_STR + bcol]     = *(const float4*)(W2 + (size_t)(kk + brow) * DIM + bcol);
        *(float4*)&sB[brow * SB_STR + bcol + 4] = *(const float4*)(W2 + (size_t)(kk + brow) * DIM + bcol + 4);
        __syncthreads();
        #pragma unroll
        for (int k8 = 0; k8 < 16; k8 += 8) {
            uint32_t a0 = __float_as_uint(sA[(mrow + g)     * SA_STR + kk + k8 + t]);
            uint32_t a1 = __float_as_uint(sA[(mrow + g + 8) * SA_STR + kk + k8 + t]);
            uint32_t a2 = __float_as_uint(sA[(mrow + g)     * SA_STR + kk + k8 + t + 4]);
            uint32_t a3 = __float_as_uint(sA[(mrow + g + 8) * SA_STR + kk + k8 + t + 4]);
            #pragma unroll
            for (int nt = 0; nt < 16; nt++) {
                int n = nt * 8 + g;
                uint32_t b0 = __float_as_uint(sB[(k8 + t)     * SB_STR + n]);
                uint32_t b1 = __float_as_uint(sB[(k8 + t + 4) * SB_STR + n]);
                mma8(acc[nt][0], acc[nt][1], acc[nt][2], acc[nt][3],
                     a0, a1, a2, a3, b0, b1);
            }
        }
        __syncthreads();
    }

    #pragma unroll
    for (int nt = 0; nt < 16; nt++) {
        int col = nt * 8 + 2 * t;
        float b0 = bias2[col], b1 = bias2[col + 1];
        int s0 = mrow + g, s1 = mrow + g + 8;
        if (row0 + s0 < cnt) {
            float* o = g_h1 + (size_t)sNode[s0] * DIM + col;   // h2 aliases h1
            *(float2*)o = make_float2(eluf(acc[nt][0] + b0), eluf(acc[nt][1] + b1));
        }
        if (row0 + s1 < cnt) {
            float* o = g_h1 + (size_t)sNode[s1] * DIM + col;
            *(float2*)o = make_float2(eluf(acc[nt][2] + b0), eluf(acc[nt][3] + b1));
        }
    }
}

// ---------------- 4: final dot + sigmoid (+ counter reset for next call) -----
__global__ __launch_bounds__(256)
void final_k(const int* __restrict__ uidx, const int* __restrict__ iidx,
             float* __restrict__ res)
{
    if (blockIdx.x == 0 && threadIdx.x == 0) { g_cnt1 = 0; g_cnt2 = 0; }
    int b    = (blockIdx.x * blockDim.x + threadIdx.x) >> 5;
    int lane = threadIdx.x & 31;
    if (b >= BATCH) return;
    const float* ru = g_h1 + (size_t)uidx[b] * DIM;
    const float* rv = g_h1 + (size_t)(iidx[b] + NUM_USERS) * DIM;
    float dot = ru[lane]      * rv[lane]
              + ru[lane + 32] * rv[lane + 32]
              + ru[lane + 64] * rv[lane + 64]
              + ru[lane + 96] * rv[lane + 96];
    dot = wsum(dot);
    if (lane == 0) res[b] = 1.f / (1.f + expf(-dot));
}

// ---------------- launch -----------------------------------------------------
extern "C" void kernel_launch(void* const* d_in, const int* in_sizes, int n_in,
                              void* d_out, int out_size)
{
    const int*   uidx  = (const int*)  d_in[0];
    const int*   iidx  = (const int*)  d_in[1];
    const int*   ei    = (const int*)  d_in[2];
    const float* userT = (const float*)d_in[3];
    const float* itemT = (const float*)d_in[4];
    const float* W1    = (const float*)d_in[5];
    const float* attS1 = (const float*)d_in[6];
    const float* attD1 = (const float*)d_in[7];
    const float* bias1 = (const float*)d_in[8];
    const float* W2    = (const float*)d_in[9];
    const float* attS2 = (const float*)d_in[10];
    const float* attD2 = (const float*)d_in[11];
    const float* bias2 = (const float*)d_in[12];
    float* res = (float*)d_out;

    cudaFuncSetAttribute(fused1_k, cudaFuncAttributeMaxDynamicSharedMemorySize, SMEM1);
    cudaFuncSetAttribute(fused2_k, cudaFuncAttributeMaxDynamicSharedMemorySize, SMEM2);

    prep_k  <<<NBLK, 256>>>(W1, attS1, attD1, W2, attS2, attD2, uidx, iidx, ei);
    fused1_k<<<(MAXL1 + 31) / 32,   256, SMEM1>>>(userT, itemT, ei, W1, bias1);
    fused2_k<<<(MAXL2 + 127) / 128, 256, SMEM2>>>(ei, W2, bias2);
    final_k <<<(BATCH + 7) / 8, 256>>>(uidx, iidx, res);
}